// round 7
// baseline (speedup 1.0000x reference)
#include <cuda_runtime.h>
#include <cstdint>

#define N0 4096
#define N1 8192
#define N2 4096
#define GRID 148

// Scratch (allocation-free: __device__ global)
__device__ __align__(16) float g_x1[N1];

__device__ __forceinline__ float warp_sum(float v) {
#pragma unroll
    for (int o = 16; o > 0; o >>= 1) v += __shfl_xor_sync(0xffffffffu, v, o);
    return v;
}

__device__ __forceinline__ uint32_t smem_u32(const void* p) {
    return (uint32_t)__cvta_generic_to_shared(p);
}
__device__ __forceinline__ void cp_async16(uint32_t dst, const void* src) {
    asm volatile("cp.async.cg.shared.global [%0], [%1], 16;" :: "r"(dst), "l"(src));
}
#define CP_COMMIT() asm volatile("cp.async.commit_group;" ::: "memory")
#define CP_WAIT(n)  asm volatile("cp.async.wait_group %0;" :: "n"(n) : "memory")

// Block-wide reduction of 8 partial sums (1024 threads). Deterministic.
__device__ __forceinline__ void block_reduce8(float s[8], float (*sh)[32], float* s_sums)
{
    int tid = threadIdx.x;
    int w = tid >> 5, l = tid & 31;
#pragma unroll
    for (int k = 0; k < 8; k++) s[k] = warp_sum(s[k]);
    if (l == 0) {
#pragma unroll
        for (int k = 0; k < 8; k++) sh[k][w] = s[k];
    }
    __syncthreads();
    if (tid < 256) {
        int k = tid >> 5, ln = tid & 31;
        float v = warp_sum(sh[k][ln]);
        if (ln == 0) s_sums[k] = v;
    }
}

__device__ __forceinline__ float heb_row_val(
    int row,
    const float* __restrict__ act_post,
    const float* __restrict__ b_post,
    const float* __restrict__ c_post,
    const float* __restrict__ d_post,
    const float* __restrict__ e_post,
    const float* __restrict__ sums)
{
    float P = b_post[row] * act_post[row];
    float C = c_post[row] * act_post[row];
    float D = d_post[row];
    float E = e_post[row];
    return 0.5f * (sums[0] + P * sums[1] + C * sums[2] + D * sums[3]
          + E * (sums[4] + P * sums[5] + C * sums[6] + D * sums[7]));
}

__device__ __forceinline__ void heb_partial4(
    float s[8], float4 xv, float4 actv, float4 av, float4 cv, float4 dv, float4 ev)
{
    float xs[4]  = {xv.x, xv.y, xv.z, xv.w};
    float acs[4] = {actv.x, actv.y, actv.z, actv.w};
    float as[4]  = {av.x, av.y, av.z, av.w};
    float cs[4]  = {cv.x, cv.y, cv.z, cv.w};
    float ds[4]  = {dv.x, dv.y, dv.z, dv.w};
    float es[4]  = {ev.x, ev.y, ev.z, ev.w};
#pragma unroll
    for (int j = 0; j < 4; j++) {
        float x = xs[j], e = es[j];
        float p = as[j] * acs[j];
        float c = cs[j] * acs[j];
        float d = ds[j];
        s[0] += e * p * x;  s[1] += e * x;
        s[2] += e * c * x;  s[3] += e * d * x;
        s[4] += p * x;      s[5] += x;
        s[6] += c * x;      s[7] += d * x;
    }
}

// ---------------------------------------------------------------------------
// Fused GEMV, reduction-free mainloop.
//   Tile = 32 rows x 64 float4 (32 KB), smem rows padded to 65 f4.
//   Fetch:   thread(warp=fr, lane=p) copies row fr, f4-cols {p, p+32}  (coalesced)
//   Consume: thread(warp=w, lane=l) FMAs row l, f4-cols {2w, 2w+1}     (no shfl)
//   4-deep cp.async ring, 1 barrier per chunk. Cross-warp combine once/group.
// ---------------------------------------------------------------------------
template <int NCOL4, int NROWS_OUT, bool TANH_IN, bool TANH_OUT>
__device__ __forceinline__ void gemv_fused(
    const float* __restrict__ W,
    const float* __restrict__ xin_src,
    const float* __restrict__ act_pre,
    const float* __restrict__ a_pre,
    const float* __restrict__ c_pre,
    const float* __restrict__ d_pre,
    const float* __restrict__ e_pre,
    const float* __restrict__ act_post,
    const float* __restrict__ b_post,
    const float* __restrict__ c_post,
    const float* __restrict__ d_post,
    const float* __restrict__ e_post,
    float* __restrict__ out)
{
    constexpr int CPG = NCOL4 / 64;              // chunks per 32-row group
    constexpr int LG_CPG = (CPG == 16) ? 4 : 5;
    constexpr int NBUF = 4;
    constexpr int SLOT_F4 = 32 * 65;             // padded tile, in float4

    extern __shared__ float4 dyn[];
    float4* bufs = dyn;                          // NBUF * SLOT_F4
    float4* sx   = dyn + NBUF * SLOT_F4;         // NCOL4 (<= 2048)

    __shared__ float sh[8][32];
    __shared__ float s_sums[8];
    __shared__ float s_heb[64];
    __shared__ float s_red[32][33];

    const int tid  = threadIdx.x;
    const int lane = tid & 31;
    const int warp = tid >> 5;

    const int r_lo = (int)(((long long)blockIdx.x * NROWS_OUT) / GRID);
    const int r_hi = (int)(((long long)(blockIdx.x + 1) * NROWS_OUT) / GRID);
    const int nrows = r_hi - r_lo;
    const int ngroups = (nrows + 31) >> 5;
    const int totalChunks = ngroups << LG_CPG;

    const float4* Wb = reinterpret_cast<const float4*>(W) + (size_t)r_lo * NCOL4;
    const uint32_t sbase = smem_u32(bufs);

    // Fetch roles: this thread copies row `warp` of each group, f4-cols lane & lane+32.
    auto issue_chunk = [&](int pc) {
        if (pc < totalChunks) {
            int g  = pc >> LG_CPG;
            int cg = pc & (CPG - 1);
            int rowg = (g << 5) + warp;
            if (rowg < nrows) {
                const float4* src = Wb + (size_t)rowg * NCOL4 + (cg << 6) + lane;
                uint32_t dst = sbase +
                    (uint32_t)((pc & (NBUF - 1)) * SLOT_F4 + warp * 65 + lane) * 16u;
                cp_async16(dst, src);
                cp_async16(dst + 32u * 16u, src + 32);
            }
        }
        CP_COMMIT();
    };

    // Prologue: start DRAM immediately (3 chunks in flight).
    issue_chunk(0); issue_chunk(1); issue_chunk(2);

    // Phase 1: stage x into smem (+tanh for layer 0), Hebbian pre-side sums.
    {
        float s[8] = {0.f, 0.f, 0.f, 0.f, 0.f, 0.f, 0.f, 0.f};
        const float4* x4 = reinterpret_cast<const float4*>(xin_src);
        for (int i = tid; i < NCOL4; i += 1024) {
            float4 xv = x4[i];
            if (TANH_IN)
                xv = make_float4(tanhf(xv.x), tanhf(xv.y), tanhf(xv.z), tanhf(xv.w));
            sx[i] = xv;
            float4 actv = reinterpret_cast<const float4*>(act_pre)[i];
            float4 av   = reinterpret_cast<const float4*>(a_pre)[i];
            float4 cv   = reinterpret_cast<const float4*>(c_pre)[i];
            float4 dv   = reinterpret_cast<const float4*>(d_pre)[i];
            float4 ev   = reinterpret_cast<const float4*>(e_pre)[i];
            heb_partial4(s, xv, actv, av, cv, dv, ev);
        }
        block_reduce8(s, sh, s_sums);
    }
    __syncthreads();
    if (tid < nrows) {
        s_heb[tid] = heb_row_val(r_lo + tid, act_post, b_post, c_post, d_post,
                                 e_post, s_sums);
    }
    // (first in-loop barrier orders s_heb/sx before any consume)

    // Mainloop: consume role = (row lane, f4-cols 2*warp, 2*warp+1).
    float acc = 0.f;
    const int cw2 = warp << 1;

    for (int cc = 0; cc < totalChunks; cc++) {
        CP_WAIT(2);                 // chunk cc's data complete (all threads' copies)
        __syncthreads();            // ...and visible block-wide; prev slot drained
        issue_chunk(cc + NBUF - 1); // refill slot (cc-1)%NBUF

        const int cig = cc & (CPG - 1);
        const float4* b = bufs + (size_t)((cc & (NBUF - 1)) * SLOT_F4 + lane * 65 + cw2);
        float4 w0 = b[0];
        float4 w1 = b[1];
        const float4* xp = sx + (cig << 6) + cw2;
        float4 x0 = xp[0];          // broadcast (lane-uniform)
        float4 x1 = xp[1];
        acc = fmaf(w0.x, x0.x, acc);
        acc = fmaf(w0.y, x0.y, acc);
        acc = fmaf(w0.z, x0.z, acc);
        acc = fmaf(w0.w, x0.w, acc);
        acc = fmaf(w1.x, x1.x, acc);
        acc = fmaf(w1.y, x1.y, acc);
        acc = fmaf(w1.z, x1.z, acc);
        acc = fmaf(w1.w, x1.w, acc);

        if (cig == CPG - 1) {
            // End of group: combine 32 column-stripe partials per row.
            s_red[lane][warp] = acc;   // [row][stripe]
            acc = 0.f;
            __syncthreads();
            int g = cc >> LG_CPG;
            int rowg = (g << 5) + warp;     // warp w owns row w of this group
            float v = warp_sum(s_red[warp][lane]);
            if (lane == 0 && rowg < nrows) {
                float y = v + s_heb[rowg];
                out[r_lo + rowg] = TANH_OUT ? tanhf(y) : y;
            }
        }
    }
}

// ---------------------------------------------------------------------------
__global__ void __launch_bounds__(1024, 1) k_gemv0(
    const float* __restrict__ W0,
    const float* __restrict__ inputs,
    const float* __restrict__ act0,
    const float* __restrict__ a0,
    const float* __restrict__ c0,
    const float* __restrict__ d0,
    const float* __restrict__ e0,
    const float* __restrict__ act1,
    const float* __restrict__ b1,
    const float* __restrict__ c1,
    const float* __restrict__ d1,
    const float* __restrict__ e1)
{
    gemv_fused<N0 / 4, N1, true, true>(
        W0, inputs, act0, a0, c0, d0, e0,
        act1, b1, c1, d1, e1, g_x1);
}

__global__ void __launch_bounds__(1024, 1) k_gemv1(
    const float* __restrict__ W1,
    const float* __restrict__ act1,
    const float* __restrict__ a1,
    const float* __restrict__ c1,
    const float* __restrict__ d1,
    const float* __restrict__ e1,
    const float* __restrict__ act2,
    const float* __restrict__ b2,
    const float* __restrict__ c2,
    const float* __restrict__ d2,
    const float* __restrict__ e2,
    float* __restrict__ out)
{
    gemv_fused<N1 / 4, N2, false, false>(
        W1, g_x1, act1, a1, c1, d1, e1,
        act2, b2, c2, d2, e2, out);
}

// ---------------------------------------------------------------------------
extern "C" void kernel_launch(void* const* d_in, const int* in_sizes, int n_in,
                              void* d_out, int out_size)
{
    const float* inputs = (const float*)d_in[0];
    const float* act0   = (const float*)d_in[1];
    const float* act1   = (const float*)d_in[2];
    const float* act2   = (const float*)d_in[3];
    const float* W0     = (const float*)d_in[4];
    const float* W1     = (const float*)d_in[5];
    const float* a0     = (const float*)d_in[6];
    const float* c0     = (const float*)d_in[7];
    const float* d0     = (const float*)d_in[8];
    const float* e0     = (const float*)d_in[9];
    const float* a1     = (const float*)d_in[10];
    const float* b1     = (const float*)d_in[11];
    const float* c1     = (const float*)d_in[12];
    const float* d1     = (const float*)d_in[13];
    const float* e1     = (const float*)d_in[14];
    const float* b2     = (const float*)d_in[15];
    const float* c2     = (const float*)d_in[16];
    const float* d2     = (const float*)d_in[17];
    const float* e2     = (const float*)d_in[18];
    float* out = (float*)d_out;

    // 4 ring slots (32x65 f4) + x staging (2048 f4) = 165,888 bytes dynamic smem.
    const int SMEM_DYN = (4 * 32 * 65 + 2048) * (int)sizeof(float4);
    cudaFuncSetAttribute(k_gemv0, cudaFuncAttributeMaxDynamicSharedMemorySize, SMEM_DYN);
    cudaFuncSetAttribute(k_gemv1, cudaFuncAttributeMaxDynamicSharedMemorySize, SMEM_DYN);

    k_gemv0<<<GRID, 1024, SMEM_DYN>>>(W0, inputs, act0, a0, c0, d0, e0,
                                      act1, b1, c1, d1, e1);
    k_gemv1<<<GRID, 1024, SMEM_DYN>>>(W1, act1, a1, c1, d1, e1,
                                      act2, b2, c2, d2, e2, out);
}

// round 8
// speedup vs baseline: 1.0634x; 1.0634x over previous
#include <cuda_runtime.h>
#include <cstdint>

#define N0 4096
#define N1 8192
#define N2 4096
#define NBLK 296           // 2 CTAs per SM
#define BLK 512

// Scratch (allocation-free: __device__ global)
__device__ __align__(16) float g_x1[N1];

__device__ __forceinline__ float warp_sum(float v) {
#pragma unroll
    for (int o = 16; o > 0; o >>= 1) v += __shfl_xor_sync(0xffffffffu, v, o);
    return v;
}

__device__ __forceinline__ uint32_t smem_u32(const void* p) {
    return (uint32_t)__cvta_generic_to_shared(p);
}
__device__ __forceinline__ void cp_async16(uint32_t dst, const void* src) {
    asm volatile("cp.async.cg.shared.global [%0], [%1], 16;" :: "r"(dst), "l"(src));
}
#define CP_COMMIT() asm volatile("cp.async.commit_group;" ::: "memory")
#define CP_WAIT(n)  asm volatile("cp.async.wait_group %0;" :: "n"(n) : "memory")

// Block-wide reduction of 8 partial sums (512 threads / 16 warps). Deterministic.
__device__ __forceinline__ void block_reduce8(float s[8], float (*sh)[16], float* s_sums)
{
    int tid = threadIdx.x;
    int w = tid >> 5, l = tid & 31;
#pragma unroll
    for (int k = 0; k < 8; k++) s[k] = warp_sum(s[k]);
    if (l == 0) {
#pragma unroll
        for (int k = 0; k < 8; k++) sh[k][w] = s[k];
    }
    __syncthreads();
    if (tid < 256) {
        int k = tid >> 5, ln = tid & 31;
        float v = (ln < 16) ? sh[k][ln] : 0.f;
        v = warp_sum(v);
        if (ln == 0) s_sums[k] = v;
    }
}

__device__ __forceinline__ float heb_row_val(
    int row,
    const float* __restrict__ act_post,
    const float* __restrict__ b_post,
    const float* __restrict__ c_post,
    const float* __restrict__ d_post,
    const float* __restrict__ e_post,
    const float* __restrict__ sums)
{
    float P = b_post[row] * act_post[row];
    float C = c_post[row] * act_post[row];
    float D = d_post[row];
    float E = e_post[row];
    return 0.5f * (sums[0] + P * sums[1] + C * sums[2] + D * sums[3]
          + E * (sums[4] + P * sums[5] + C * sums[6] + D * sums[7]));
}

__device__ __forceinline__ void heb_partial4(
    float s[8], float4 xv, float4 actv, float4 av, float4 cv, float4 dv, float4 ev)
{
    float xs[4]  = {xv.x, xv.y, xv.z, xv.w};
    float acs[4] = {actv.x, actv.y, actv.z, actv.w};
    float as[4]  = {av.x, av.y, av.z, av.w};
    float cs[4]  = {cv.x, cv.y, cv.z, cv.w};
    float ds[4]  = {dv.x, dv.y, dv.z, dv.w};
    float es[4]  = {ev.x, ev.y, ev.z, ev.w};
#pragma unroll
    for (int j = 0; j < 4; j++) {
        float x = xs[j], e = es[j];
        float p = as[j] * acs[j];
        float c = cs[j] * acs[j];
        float d = ds[j];
        s[0] += e * p * x;  s[1] += e * x;
        s[2] += e * c * x;  s[3] += e * d * x;
        s[4] += p * x;      s[5] += x;
        s[6] += c * x;      s[7] += d * x;
    }
}

// ---------------------------------------------------------------------------
// Fused GEMV (R5 architecture @ 2 CTAs/SM): cp.async row pipeline NBUF deep,
// x in registers, thread t owns f4-columns {t, t+512, ...}. Per-row shfl
// reduce; no block barrier on the data path.
// ---------------------------------------------------------------------------
template <int NCOL4, int NROWS_OUT, bool TANH_IN, bool TANH_OUT, int NBUF>
__device__ __forceinline__ void gemv_fused(
    const float* __restrict__ W,
    const float* __restrict__ xin_src,
    const float* __restrict__ act_pre,
    const float* __restrict__ a_pre,
    const float* __restrict__ c_pre,
    const float* __restrict__ d_pre,
    const float* __restrict__ e_pre,
    const float* __restrict__ act_post,
    const float* __restrict__ b_post,
    const float* __restrict__ c_post,
    const float* __restrict__ d_post,
    const float* __restrict__ e_post,
    float* __restrict__ out)
{
    constexpr int F4PT = NCOL4 / BLK;     // float4 per thread per row (2 or 4)

    extern __shared__ float4 dynbuf[];    // NBUF * NCOL4 float4 (96 KB)
    __shared__ float sh[8][16];
    __shared__ float s_sums[8];
    __shared__ float s_heb[32];
    __shared__ float s_part[2][8][16];

    int tid = threadIdx.x;
    int lane = tid & 31;
    int warp = tid >> 5;

    int r_lo = (int)(((long long)blockIdx.x * NROWS_OUT) / NBLK);
    int r_hi = (int)(((long long)(blockIdx.x + 1) * NROWS_OUT) / NBLK);
    int nrows = r_hi - r_lo;

    const float4* Wb = reinterpret_cast<const float4*>(W) + (size_t)r_lo * NCOL4;
    uint32_t sbase = smem_u32(dynbuf);

    // Kick off DRAM immediately: prefetch first NBUF rows.
#pragma unroll
    for (int r = 0; r < NBUF; r++) {
        if (r < nrows) {
#pragma unroll
            for (int j = 0; j < F4PT; j++) {
                int col = tid + j * BLK;
                cp_async16(sbase + (uint32_t)(r * NCOL4 + col) * 16u,
                           Wb + (size_t)r * NCOL4 + col);
            }
        }
        CP_COMMIT();
    }

    // x into registers (+tanh), Hebbian pre-side sums (overlaps prefetch).
    float4 xr[F4PT];
    {
        float s[8] = {0.f, 0.f, 0.f, 0.f, 0.f, 0.f, 0.f, 0.f};
#pragma unroll
        for (int j = 0; j < F4PT; j++) {
            int i = tid + j * BLK;
            float4 xv = reinterpret_cast<const float4*>(xin_src)[i];
            if (TANH_IN)
                xv = make_float4(tanhf(xv.x), tanhf(xv.y), tanhf(xv.z), tanhf(xv.w));
            xr[j] = xv;
            float4 actv = reinterpret_cast<const float4*>(act_pre)[i];
            float4 av   = reinterpret_cast<const float4*>(a_pre)[i];
            float4 cv   = reinterpret_cast<const float4*>(c_pre)[i];
            float4 dv   = reinterpret_cast<const float4*>(d_pre)[i];
            float4 ev   = reinterpret_cast<const float4*>(e_pre)[i];
            heb_partial4(s, xv, actv, av, cv, dv, ev);
        }
        block_reduce8(s, sh, s_sums);
    }
    __syncthreads();
    if (tid < nrows) {
        s_heb[tid] = heb_row_val(r_lo + tid, act_post, b_post, c_post, d_post,
                                 e_post, s_sums);
    }
    __syncthreads();

    // Rolling state.
    int rdSlot = 0;
    int wrSlot = 0;                               // row NBUF writes slot 0
    const float4* gsrc = Wb + (size_t)NBUF * NCOL4 + tid;

    int par = 0;
    for (int r = 0; r < nrows; r++) {
        CP_WAIT(NBUF - 1);

        const float4* buf = dynbuf + (size_t)rdSlot * NCOL4;
        float4 wv[F4PT];
#pragma unroll
        for (int j = 0; j < F4PT; j++) wv[j] = buf[tid + j * BLK];
        rdSlot = (rdSlot + 1 == NBUF) ? 0 : rdSlot + 1;

        float acc = 0.f;
#pragma unroll
        for (int j = 0; j < F4PT; j++) {
            acc = fmaf(wv[j].x, xr[j].x, acc);
            acc = fmaf(wv[j].y, xr[j].y, acc);
            acc = fmaf(wv[j].z, xr[j].z, acc);
            acc = fmaf(wv[j].w, xr[j].w, acc);
        }
        float p = warp_sum(acc);
        if (lane == 0) s_part[par][r & 7][warp] = p;

        // Prefetch row r+NBUF (empty commit at tail keeps group cadence).
        if (r + NBUF < nrows) {
            uint32_t wbase = sbase + (uint32_t)(wrSlot * NCOL4 + tid) * 16u;
#pragma unroll
            for (int j = 0; j < F4PT; j++)
                cp_async16(wbase + (uint32_t)(j * BLK) * 16u, gsrc + j * BLK);
        }
        wrSlot = (wrSlot + 1 == NBUF) ? 0 : wrSlot + 1;
        gsrc += NCOL4;
        CP_COMMIT();

        if ((r & 7) == 7 || r == nrows - 1) {
            __syncthreads();
            if (tid < 256) {
                int rr = (r & ~7) + warp;     // warp = 0..7 here
                if (rr < nrows) {
                    float v = (lane < 16) ? s_part[par][warp][lane] : 0.f;
                    v = warp_sum(v);
                    if (lane == 0) {
                        float y = v + s_heb[rr];
                        out[r_lo + rr] = TANH_OUT ? tanhf(y) : y;
                    }
                }
            }
            par ^= 1;
        }
    }
}

// ---------------------------------------------------------------------------
__global__ void __launch_bounds__(BLK, 2) k_gemv0(
    const float* __restrict__ W0,
    const float* __restrict__ inputs,
    const float* __restrict__ act0,
    const float* __restrict__ a0,
    const float* __restrict__ c0,
    const float* __restrict__ d0,
    const float* __restrict__ e0,
    const float* __restrict__ act1,
    const float* __restrict__ b1,
    const float* __restrict__ c1,
    const float* __restrict__ d1,
    const float* __restrict__ e1)
{
    gemv_fused<N0 / 4, N1, true, true, 6>(
        W0, inputs, act0, a0, c0, d0, e0,
        act1, b1, c1, d1, e1, g_x1);
}

__global__ void __launch_bounds__(BLK, 2) k_gemv1(
    const float* __restrict__ W1,
    const float* __restrict__ act1,
    const float* __restrict__ a1,
    const float* __restrict__ c1,
    const float* __restrict__ d1,
    const float* __restrict__ e1,
    const float* __restrict__ act2,
    const float* __restrict__ b2,
    const float* __restrict__ c2,
    const float* __restrict__ d2,
    const float* __restrict__ e2,
    float* __restrict__ out)
{
    gemv_fused<N1 / 4, N2, false, false, 3>(
        W1, g_x1, act1, a1, c1, d1, e1,
        act2, b2, c2, d2, e2, out);
}

// ---------------------------------------------------------------------------
extern "C" void kernel_launch(void* const* d_in, const int* in_sizes, int n_in,
                              void* d_out, int out_size)
{
    const float* inputs = (const float*)d_in[0];
    const float* act0   = (const float*)d_in[1];
    const float* act1   = (const float*)d_in[2];
    const float* act2   = (const float*)d_in[3];
    const float* W0     = (const float*)d_in[4];
    const float* W1     = (const float*)d_in[5];
    const float* a0     = (const float*)d_in[6];
    const float* c0     = (const float*)d_in[7];
    const float* d0     = (const float*)d_in[8];
    const float* e0     = (const float*)d_in[9];
    const float* a1     = (const float*)d_in[10];
    const float* b1     = (const float*)d_in[11];
    const float* c1     = (const float*)d_in[12];
    const float* d1     = (const float*)d_in[13];
    const float* e1     = (const float*)d_in[14];
    const float* b2     = (const float*)d_in[15];
    const float* c2     = (const float*)d_in[16];
    const float* d2     = (const float*)d_in[17];
    const float* e2     = (const float*)d_in[18];
    float* out = (float*)d_out;

    // 6 buffers * 1024 f4 (gemv0) == 3 buffers * 2048 f4 (gemv1) == 96 KB.
    const int SMEM_DYN = 6 * (N0 / 4) * (int)sizeof(float4);
    cudaFuncSetAttribute(k_gemv0, cudaFuncAttributeMaxDynamicSharedMemorySize, SMEM_DYN);
    cudaFuncSetAttribute(k_gemv1, cudaFuncAttributeMaxDynamicSharedMemorySize, SMEM_DYN);

    k_gemv0<<<NBLK, BLK, SMEM_DYN>>>(W0, inputs, act0, a0, c0, d0, e0,
                                     act1, b1, c1, d1, e1);
    k_gemv1<<<NBLK, BLK, SMEM_DYN>>>(W1, act1, a1, c1, d1, e1,
                                     act2, b2, c2, d2, e2, out);
}